// round 1
// baseline (speedup 1.0000x reference)
#include <cuda_runtime.h>

#define H   8
#define LQ  384
#define LK  384
#define DQ  32
#define DV  32
#define DC  64
#define BS  2

// 2 * log2(e): folds tanh(x) = 1 - 2/(exp(2x)+1) into ex2.approx directly
#define K2 2.8853900817779268f
#define LOG2E 1.4426950408889634f

// scratch (no allocations allowed): A'[b,h,q,e], C'^T[b,h,e,k]
__device__ float g_A [BS * H * LQ * DC];
__device__ float g_Ct[BS * H * DC * LK];

__device__ __forceinline__ float ex2a(float x) {
    float r; asm("ex2.approx.f32 %0, %1;" : "=f"(r) : "f"(x)); return r;
}
__device__ __forceinline__ float rcpa(float x) {
    float r; asm("rcp.approx.f32 %0, %1;" : "=f"(r) : "f"(x)); return r;
}

// A'[((b*H+h)*LQ+q)*DC + e] = K2 * (sum_d q[b,q,h*DQ+d] * w1[h,d,e] + b1[h,e])
__global__ void precompute_qw(const float* __restrict__ q,
                              const float* __restrict__ w1,
                              const float* __restrict__ b1) {
    int idx = blockIdx.x * blockDim.x + threadIdx.x;   // BS*H*LQ*DC threads
    int e   = idx & (DC - 1);
    int row = idx >> 6;              // (b*H+h)*LQ + q
    int qi  = row % LQ;
    int bh  = row / LQ;
    int h   = bh & (H - 1);
    int b   = bh >> 3;
    const float* qrow = q + ((size_t)(b * LQ + qi)) * (H * DQ) + h * DQ;
    const float* w    = w1 + h * DC * DC + e;          // w1[h, d, e], top half d in [0,DQ)
    float acc = b1[h * DC + e];
#pragma unroll
    for (int d = 0; d < DQ; d++) acc = fmaf(qrow[d], w[d * DC], acc);
    g_A[idx] = K2 * acc;
}

// C'^T[((b*H+h)*DC+e)*LK + k] = K2 * sum_d k[b,k,h*DQ+d] * w1[h,DQ+d,e]
__global__ void precompute_kw(const float* __restrict__ kin,
                              const float* __restrict__ w1) {
    int idx  = blockIdx.x * blockDim.x + threadIdx.x;  // BS*H*DC*LK threads
    int kk   = idx % LK;
    int rest = idx / LK;             // (b*H+h)*DC + e
    int e    = rest & (DC - 1);
    int bh   = rest >> 6;
    int h    = bh & (H - 1);
    int b    = bh >> 3;
    const float* krow = kin + ((size_t)(b * LK + kk)) * (H * DQ) + h * DQ;
    const float* w    = w1 + h * DC * DC + DQ * DC + e;  // bottom half rows
    float acc = 0.f;
#pragma unroll
    for (int d = 0; d < DQ; d++) acc = fmaf(krow[d], w[d * DC], acc);
    g_Ct[idx] = K2 * acc;
}

// One warp per (b,h,q) row. 8 warps/block -> 8 consecutive q of one (b,h)
// so the (b,h) C'^T slice (96KB) gets L1 reuse.
__global__ void __launch_bounds__(256)
attn_kernel(const float* __restrict__ w2, const float* __restrict__ v,
            const int* __restrict__ qlen, const int* __restrict__ klen,
            float* __restrict__ out, float* __restrict__ att) {
    __shared__ float2 sAW[8][DC];     // {A'[e], w2[e]} per warp
    __shared__ float  sS [8][LK];     // scores -> probs per warp

    int warp = threadIdx.x >> 5;
    int lane = threadIdx.x & 31;
    int row  = blockIdx.x * 8 + warp;           // (b*H+h)*LQ + q
    int qi   = row % LQ;
    int bh   = row / LQ;
    int h    = bh & (H - 1);
    int b    = bh >> 3;

    const float* Arow = g_A + (size_t)row * DC;
    const float* w2h  = w2 + h * DC;
    sAW[warp][lane]      = make_float2(Arow[lane],      w2h[lane]);
    sAW[warp][lane + 32] = make_float2(Arow[lane + 32], w2h[lane + 32]);
    __syncwarp();

    const int kl  = klen[b];
    const int nkc = (kl + 31) >> 5;
    const float* ct = g_Ct + (size_t)bh * DC * LK;   // [e][k]

    // ---- scores: s[k] = sum_e w2[e] * tanh_fast(A'[e] + C'[e,k]) ----
    float m = -3.4e38f;
    for (int c = 0; c < nkc; c++) {
        int   kk  = (c << 5) + lane;
        float acc = 0.f;
#pragma unroll 16
        for (int e = 0; e < DC; e++) {
            float2 aw = sAW[warp][e];
            float  t  = ex2a(aw.x + ct[e * LK + kk]);    // exp(2x)
            float  r  = rcpa(t + 1.0f);
            float  th = fmaf(-2.0f, r, 1.0f);            // tanh(x)
            acc = fmaf(aw.y, th, acc);
        }
        sS[warp][kk] = acc;
        if (kk < kl) m = fmaxf(m, acc);
    }
#pragma unroll
    for (int o = 16; o; o >>= 1) m = fmaxf(m, __shfl_xor_sync(0xffffffffu, m, o));

    // ---- softmax ----
    float sum = 0.f;
    for (int c = 0; c < nkc; c++) {
        int   kk = (c << 5) + lane;
        float p  = (kk < kl) ? ex2a((sS[warp][kk] - m) * LOG2E) : 0.f;
        sS[warp][kk] = p;
        sum += p;
    }
#pragma unroll
    for (int o = 16; o; o >>= 1) sum += __shfl_xor_sync(0xffffffffu, sum, o);
    float rinv = 1.0f / sum;
    __syncwarp();

    // ---- write att row (zeros for masked keys; d_out is poisoned) ----
    float* attrow = att + (size_t)row * LK;
#pragma unroll
    for (int c = 0; c < LK / 32; c++) {
        int kk = (c << 5) + lane;
        attrow[kk] = (kk < kl) ? sS[warp][kk] * rinv : 0.f;
    }

    // ---- out[q, h, dv] = sum_k att[k] * v[b,k,h*DV+dv], lane = dv ----
    const float* vb = v + (size_t)b * LK * (H * DV) + h * DV + lane;
    float o = 0.f;
    int kk = 0;
    for (; kk + 4 <= kl; kk += 4) {
        o = fmaf(sS[warp][kk],     vb[(size_t)kk       * (H * DV)], o);
        o = fmaf(sS[warp][kk + 1], vb[(size_t)(kk + 1) * (H * DV)], o);
        o = fmaf(sS[warp][kk + 2], vb[(size_t)(kk + 2) * (H * DV)], o);
        o = fmaf(sS[warp][kk + 3], vb[(size_t)(kk + 3) * (H * DV)], o);
    }
    for (; kk < kl; kk++)
        o = fmaf(sS[warp][kk], vb[(size_t)kk * (H * DV)], o);
    o *= rinv;
    if (qi >= qlen[b]) o = 0.f;      // query-side mask only zeros `out`, not att
    out[((size_t)(b * LQ + qi)) * (H * DV) + h * DV + lane] = o;
}

extern "C" void kernel_launch(void* const* d_in, const int* in_sizes, int n_in,
                              void* d_out, int out_size) {
    const float* q    = (const float*)d_in[0];
    const float* k    = (const float*)d_in[1];
    const float* v    = (const float*)d_in[2];
    const int*   qlen = (const int*)  d_in[3];
    const int*   klen = (const int*)  d_in[4];
    const float* w1   = (const float*)d_in[5];
    const float* b1   = (const float*)d_in[6];
    const float* w2   = (const float*)d_in[7];

    float* out = (float*)d_out;
    float* att = out + (size_t)BS * LQ * H * DV;   // outputs concatenated: (out, att)

    precompute_qw<<<(BS * H * LQ * DC) / 256, 256>>>(q, w1, b1);
    precompute_kw<<<(BS * H * DC * LK) / 256, 256>>>(k, w1);
    attn_kernel<<<(BS * H * LQ) / 8, 256>>>(w2, v, qlen, klen, out, att);
}

// round 2
// speedup vs baseline: 1.2566x; 1.2566x over previous
#include <cuda_runtime.h>

#define H   8
#define LQ  384
#define LK  384
#define DQ  32
#define DV  32
#define DC  64
#define BS  2

#define K2 2.8853900817779268f   // 2*log2(e)

#define NQW (BS * H * LQ * DC)   // 393216
#define NKW (BS * H * DC * LK)   // 393216

// scratch: A'[b,h,q,e] = K2*(q@W1_top + b1);  C'^T[b,h,e,k] = K2*(k@W1_bot)
__device__ float g_A [BS * H * LQ * DC];
__device__ float g_Ct[BS * H * DC * LK];

__device__ __forceinline__ float ex2a(float x) {
    float r; asm("ex2.approx.f32 %0, %1;" : "=f"(r) : "f"(x)); return r;
}
__device__ __forceinline__ float rcpa(float x) {
    float r; asm("rcp.approx.f32 %0, %1;" : "=f"(r) : "f"(x)); return r;
}

// Fused precompute: first half of grid does A', second half does C'^T.
__global__ void __launch_bounds__(256)
precompute(const float* __restrict__ q, const float* __restrict__ kin,
           const float* __restrict__ w1, const float* __restrict__ b1) {
    int gid = blockIdx.x * blockDim.x + threadIdx.x;
    if (gid < NQW) {
        int idx = gid;
        int e   = idx & (DC - 1);
        int row = idx >> 6;              // (b*H+h)*LQ + q
        int qi  = row % LQ;
        int bh  = row / LQ;
        int h   = bh & (H - 1);
        int b   = bh >> 3;
        const float* qrow = q + ((size_t)(b * LQ + qi)) * (H * DQ) + h * DQ;
        const float* w    = w1 + h * DC * DC + e;
        float a0 = b1[h * DC + e], a1 = 0.f;
#pragma unroll
        for (int d = 0; d < DQ; d += 2) {
            a0 = fmaf(qrow[d],     w[d * DC],        a0);
            a1 = fmaf(qrow[d + 1], w[(d + 1) * DC],  a1);
        }
        g_A[idx] = K2 * (a0 + a1);
    } else {
        int idx  = gid - NQW;
        int kk   = idx % LK;
        int rest = idx / LK;             // (b*H+h)*DC + e
        int e    = rest & (DC - 1);
        int bh   = rest >> 6;
        int h    = bh & (H - 1);
        int b    = bh >> 3;
        const float* krow = kin + ((size_t)(b * LK + kk)) * (H * DQ) + h * DQ;
        const float* w    = w1 + h * DC * DC + DQ * DC + e;
        float a0 = 0.f, a1 = 0.f;
#pragma unroll
        for (int d = 0; d < DQ; d += 2) {
            a0 = fmaf(krow[d],     w[d * DC],       a0);
            a1 = fmaf(krow[d + 1], w[(d + 1) * DC], a1);
        }
        g_Ct[idx] = K2 * (a0 + a1);
    }
}

// One warp per (b,h,q) row; each lane owns 4 consecutive k per 128-k chunk.
// acc[k] = sum_e w2[e] * sigmoid(-2*(A+C))  ->  att = softmax(-2*acc) (shift-invariant).
__global__ void __launch_bounds__(256)
attn_kernel(const float* __restrict__ w2, const float* __restrict__ v,
            const int* __restrict__ qlen, const int* __restrict__ klen,
            float* __restrict__ out, float* __restrict__ att) {
    __shared__ float2 sAW[8][DC];     // {A'[e], w2[e]} per warp
    __shared__ float  sP [8][LK];     // unnormalized probs for AV pass

    int warp = threadIdx.x >> 5;
    int lane = threadIdx.x & 31;
    int row  = blockIdx.x * 8 + warp;           // (b*H+h)*LQ + q
    int qi   = row % LQ;
    int bh   = row / LQ;
    int h    = bh & (H - 1);
    int b    = bh >> 3;

    const float* Arow = g_A + (size_t)row * DC;
    const float* w2h  = w2 + h * DC;
    sAW[warp][lane]      = make_float2(Arow[lane],      w2h[lane]);
    sAW[warp][lane + 32] = make_float2(Arow[lane + 32], w2h[lane + 32]);
    __syncwarp();

    const int kl = klen[b];
    const float* ct = g_Ct + (size_t)bh * DC * LK;   // [e][k]

    // ---- pass 1: acc[c][j] for k = c*128 + lane*4 + j ----
    float s[3][4];
#pragma unroll
    for (int c = 0; c < 3; c++) {
        if (c * 128 < kl) {
            const float* cp = ct + c * 128 + lane * 4;
            float a0 = 0.f, a1 = 0.f, a2 = 0.f, a3 = 0.f;
#pragma unroll 16
            for (int e = 0; e < DC; e++) {
                float2 aw = sAW[warp][e];
                float4 cv = *(const float4*)(cp + e * LK);
                float t0 = ex2a(aw.x + cv.x);
                float t1 = ex2a(aw.x + cv.y);
                float t2 = ex2a(aw.x + cv.z);
                float t3 = ex2a(aw.x + cv.w);
                float r0 = rcpa(t0 + 1.f);
                float r1 = rcpa(t1 + 1.f);
                float r2 = rcpa(t2 + 1.f);
                float r3 = rcpa(t3 + 1.f);
                a0 = fmaf(aw.y, r0, a0);
                a1 = fmaf(aw.y, r1, a1);
                a2 = fmaf(aw.y, r2, a2);
                a3 = fmaf(aw.y, r3, a3);
            }
            s[c][0] = a0; s[c][1] = a1; s[c][2] = a2; s[c][3] = a3;
        } else {
            s[c][0] = s[c][1] = s[c][2] = s[c][3] = 3.4e38f;
        }
    }

    // ---- min-reduce acc over valid k (score = -2*acc, so min acc == max score) ----
    float mn = 3.4e38f;
#pragma unroll
    for (int c = 0; c < 3; c++)
#pragma unroll
        for (int j = 0; j < 4; j++) {
            int kk = c * 128 + lane * 4 + j;
            if (kk < kl) mn = fminf(mn, s[c][j]);
        }
#pragma unroll
    for (int o = 16; o; o >>= 1) mn = fminf(mn, __shfl_xor_sync(0xffffffffu, mn, o));

    // ---- pass 2: p = ex2(K2*(mn - acc)), sum, write att, stash p for AV ----
    float sum = 0.f;
    float p[3][4];
#pragma unroll
    for (int c = 0; c < 3; c++)
#pragma unroll
        for (int j = 0; j < 4; j++) {
            int kk = c * 128 + lane * 4 + j;
            float pv = (kk < kl) ? ex2a(K2 * (mn - s[c][j])) : 0.f;
            p[c][j] = pv;
            sum += pv;
        }
#pragma unroll
    for (int o = 16; o; o >>= 1) sum += __shfl_xor_sync(0xffffffffu, sum, o);
    float rinv = 1.0f / sum;

    float* attrow = att + (size_t)row * LK;
#pragma unroll
    for (int c = 0; c < 3; c++) {
        float4 pa = make_float4(p[c][0] * rinv, p[c][1] * rinv,
                                p[c][2] * rinv, p[c][3] * rinv);
        *(float4*)(attrow + c * 128 + lane * 4) = pa;
        *(float4*)(&sP[warp][c * 128 + lane * 4]) =
            make_float4(p[c][0], p[c][1], p[c][2], p[c][3]);
    }
    __syncwarp();

    // ---- AV: out[dv] = rinv * sum_k p[k] * v[b,k,h*DV+dv], lane = dv ----
    const float* vb = v + (size_t)b * LK * (H * DV) + h * DV + lane;
    float o0 = 0.f, o1 = 0.f, o2 = 0.f, o3 = 0.f;
    int kk = 0;
    for (; kk + 4 <= kl; kk += 4) {
        o0 = fmaf(sP[warp][kk],     vb[(size_t)kk       * (H * DV)], o0);
        o1 = fmaf(sP[warp][kk + 1], vb[(size_t)(kk + 1) * (H * DV)], o1);
        o2 = fmaf(sP[warp][kk + 2], vb[(size_t)(kk + 2) * (H * DV)], o2);
        o3 = fmaf(sP[warp][kk + 3], vb[(size_t)(kk + 3) * (H * DV)], o3);
    }
    for (; kk < kl; kk++)
        o0 = fmaf(sP[warp][kk], vb[(size_t)kk * (H * DV)], o0);
    float o = ((o0 + o1) + (o2 + o3)) * rinv;
    if (qi >= qlen[b]) o = 0.f;
    out[((size_t)(b * LQ + qi)) * (H * DV) + h * DV + lane] = o;
}

extern "C" void kernel_launch(void* const* d_in, const int* in_sizes, int n_in,
                              void* d_out, int out_size) {
    const float* q    = (const float*)d_in[0];
    const float* k    = (const float*)d_in[1];
    const float* v    = (const float*)d_in[2];
    const int*   qlen = (const int*)  d_in[3];
    const int*   klen = (const int*)  d_in[4];
    const float* w1   = (const float*)d_in[5];
    const float* b1   = (const float*)d_in[6];
    const float* w2   = (const float*)d_in[7];

    float* out = (float*)d_out;
    float* att = out + (size_t)BS * LQ * H * DV;

    precompute<<<(NQW + NKW) / 256, 256>>>(q, k, w1, b1);
    attn_kernel<<<(BS * H * LQ) / 8, 256>>>(w2, v, qlen, klen, out, att);
}

// round 3
// speedup vs baseline: 1.4267x; 1.1354x over previous
#include <cuda_runtime.h>

#define H   8
#define LQ  384
#define LK  384
#define DQ  32
#define DV  32
#define DC  64
#define BS  2

#define K2    2.8853900817779268f   // 2*log2(e)

#define NQW (BS * H * LQ * DC)   // 393216
#define NKW (BS * H * DC * LK)   // 393216

// scratch: g_A[b,h,q,e] = exp(2*(q@W1_top + b1));  g_Ct[b,h,e,k] = exp(2*(k@W1_bot))
__device__ float g_A [BS * H * LQ * DC];
__device__ float g_Ct[BS * H * DC * LK];

__device__ __forceinline__ float ex2a(float x) {
    float r; asm("ex2.approx.f32 %0, %1;" : "=f"(r) : "f"(x)); return r;
}
__device__ __forceinline__ float rcpa(float x) {
    float r; asm("rcp.approx.f32 %0, %1;" : "=f"(r) : "f"(x)); return r;
}

// Fused precompute: first half of grid does e^{2A}, second half does e^{2C} (transposed).
__global__ void __launch_bounds__(256)
precompute(const float* __restrict__ q, const float* __restrict__ kin,
           const float* __restrict__ w1, const float* __restrict__ b1) {
    int gid = blockIdx.x * blockDim.x + threadIdx.x;
    if (gid < NQW) {
        int idx = gid;
        int e   = idx & (DC - 1);
        int row = idx >> 6;              // (b*H+h)*LQ + q
        int qi  = row % LQ;
        int bh  = row / LQ;
        int h   = bh & (H - 1);
        int b   = bh >> 3;
        const float* qrow = q + ((size_t)(b * LQ + qi)) * (H * DQ) + h * DQ;
        const float* w    = w1 + h * DC * DC + e;
        float a0 = b1[h * DC + e], a1 = 0.f;
#pragma unroll
        for (int d = 0; d < DQ; d += 2) {
            a0 = fmaf(qrow[d],     w[d * DC],        a0);
            a1 = fmaf(qrow[d + 1], w[(d + 1) * DC],  a1);
        }
        g_A[idx] = ex2a(K2 * (a0 + a1));           // e^{2A}
    } else {
        int idx  = gid - NQW;
        int kk   = idx % LK;
        int rest = idx / LK;             // (b*H+h)*DC + e
        int e    = rest & (DC - 1);
        int bh   = rest >> 6;
        int h    = bh & (H - 1);
        int b    = bh >> 3;
        const float* krow = kin + ((size_t)(b * LK + kk)) * (H * DQ) + h * DQ;
        const float* w    = w1 + h * DC * DC + DQ * DC + e;
        float a0 = 0.f, a1 = 0.f;
#pragma unroll
        for (int d = 0; d < DQ; d += 2) {
            a0 = fmaf(krow[d],     w[d * DC],       a0);
            a1 = fmaf(krow[d + 1], w[(d + 1) * DC], a1);
        }
        g_Ct[idx] = ex2a(K2 * (a0 + a1));          // e^{2C}, [e][k] layout
    }
}

// One warp per (b,h,q) row; each lane owns 4 consecutive k per 128-k chunk.
// tanh(A+C) = 1 - 2*r where r = 1/(tA*tC + 1).
// score = sum_e w2*tanh = const - 2*sum_e w2*r  ->  softmax(-2*acc), shift-invariant:
// p = exp(2*(mn - acc)) with mn = min over valid k.
__global__ void __launch_bounds__(128)
attn_kernel(const float* __restrict__ w2, const float* __restrict__ v,
            const int* __restrict__ qlen, const int* __restrict__ klen,
            float* __restrict__ out, float* __restrict__ att) {
    __shared__ float2 sAW[4][DC];     // {tA[e], w2[e]} per warp
    __shared__ float  sP [4][LK];     // unnormalized probs for AV pass

    int warp = threadIdx.x >> 5;
    int lane = threadIdx.x & 31;
    int row  = blockIdx.x * 4 + warp;           // (b*H+h)*LQ + q
    int qi   = row % LQ;
    int bh   = row / LQ;
    int h    = bh & (H - 1);
    int b    = bh >> 3;

    const float* Arow = g_A + (size_t)row * DC;
    const float* w2h  = w2 + h * DC;
    sAW[warp][lane]      = make_float2(Arow[lane],      w2h[lane]);
    sAW[warp][lane + 32] = make_float2(Arow[lane + 32], w2h[lane + 32]);
    __syncwarp();

    const int kl = klen[b];
    const float* ct = g_Ct + (size_t)bh * DC * LK;   // [e][k]

    // ---- pass 1: acc[c][j] = sum_e w2[e] / (tA[e]*tC[e,k] + 1) ----
    float s[3][4];
#pragma unroll
    for (int c = 0; c < 3; c++) {
        if (c * 128 < kl) {
            const float* cp = ct + c * 128 + lane * 4;
            float a0 = 0.f, a1 = 0.f, a2 = 0.f, a3 = 0.f;
#pragma unroll 16
            for (int e = 0; e < DC; e++) {
                float2 aw = sAW[warp][e];
                float4 cv = *(const float4*)(cp + e * LK);
                float r0 = rcpa(fmaf(aw.x, cv.x, 1.0f));
                float r1 = rcpa(fmaf(aw.x, cv.y, 1.0f));
                float r2 = rcpa(fmaf(aw.x, cv.z, 1.0f));
                float r3 = rcpa(fmaf(aw.x, cv.w, 1.0f));
                a0 = fmaf(aw.y, r0, a0);
                a1 = fmaf(aw.y, r1, a1);
                a2 = fmaf(aw.y, r2, a2);
                a3 = fmaf(aw.y, r3, a3);
            }
            s[c][0] = a0; s[c][1] = a1; s[c][2] = a2; s[c][3] = a3;
        } else {
            s[c][0] = s[c][1] = s[c][2] = s[c][3] = 3.4e38f;
        }
    }

    // ---- min-reduce acc over valid k (score = -2*acc, so min acc == max score) ----
    float mn = 3.4e38f;
#pragma unroll
    for (int c = 0; c < 3; c++)
#pragma unroll
        for (int j = 0; j < 4; j++) {
            int kk = c * 128 + lane * 4 + j;
            if (kk < kl) mn = fminf(mn, s[c][j]);
        }
#pragma unroll
    for (int o = 16; o; o >>= 1) mn = fminf(mn, __shfl_xor_sync(0xffffffffu, mn, o));

    // ---- pass 2: p = ex2(K2*(mn - acc)) = exp(2*(mn-acc)), sum, write att ----
    float sum = 0.f;
    float p[3][4];
#pragma unroll
    for (int c = 0; c < 3; c++)
#pragma unroll
        for (int j = 0; j < 4; j++) {
            int kk = c * 128 + lane * 4 + j;
            float pv = (kk < kl) ? ex2a(K2 * (mn - s[c][j])) : 0.f;
            p[c][j] = pv;
            sum += pv;
        }
#pragma unroll
    for (int o = 16; o; o >>= 1) sum += __shfl_xor_sync(0xffffffffu, sum, o);
    float rinv = 1.0f / sum;

    float* attrow = att + (size_t)row * LK;
#pragma unroll
    for (int c = 0; c < 3; c++) {
        *(float4*)(attrow + c * 128 + lane * 4) =
            make_float4(p[c][0] * rinv, p[c][1] * rinv, p[c][2] * rinv, p[c][3] * rinv);
        *(float4*)(&sP[warp][c * 128 + lane * 4]) =
            make_float4(p[c][0], p[c][1], p[c][2], p[c][3]);
    }
    __syncwarp();

    // ---- AV: out[dv] = rinv * sum_k p[k] * v[b,k,h*DV+dv], lane = dv ----
    const float* vb = v + (size_t)b * LK * (H * DV) + h * DV + lane;
    float o0 = 0.f, o1 = 0.f, o2 = 0.f, o3 = 0.f;
    int kk = 0;
    for (; kk + 4 <= kl; kk += 4) {
        float4 pv = *(const float4*)(&sP[warp][kk]);
        o0 = fmaf(pv.x, vb[(size_t)kk       * (H * DV)], o0);
        o1 = fmaf(pv.y, vb[(size_t)(kk + 1) * (H * DV)], o1);
        o2 = fmaf(pv.z, vb[(size_t)(kk + 2) * (H * DV)], o2);
        o3 = fmaf(pv.w, vb[(size_t)(kk + 3) * (H * DV)], o3);
    }
    for (; kk < kl; kk++)
        o0 = fmaf(sP[warp][kk], vb[(size_t)kk * (H * DV)], o0);
    float o = ((o0 + o1) + (o2 + o3)) * rinv;
    if (qi >= qlen[b]) o = 0.f;
    out[((size_t)(b * LQ + qi)) * (H * DV) + h * DV + lane] = o;
}

extern "C" void kernel_launch(void* const* d_in, const int* in_sizes, int n_in,
                              void* d_out, int out_size) {
    const float* q    = (const float*)d_in[0];
    const float* k    = (const float*)d_in[1];
    const float* v    = (const float*)d_in[2];
    const int*   qlen = (const int*)  d_in[3];
    const int*   klen = (const int*)  d_in[4];
    const float* w1   = (const float*)d_in[5];
    const float* b1   = (const float*)d_in[6];
    const float* w2   = (const float*)d_in[7];

    float* out = (float*)d_out;
    float* att = out + (size_t)BS * LQ * H * DV;

    precompute<<<(NQW + NKW) / 256, 256>>>(q, k, w1, b1);
    attn_kernel<<<(BS * H * LQ) / 4, 128>>>(w2, v, qlen, klen, out, att);
}

// round 4
// speedup vs baseline: 1.5446x; 1.0826x over previous
#include <cuda_runtime.h>

#define H   8
#define LQ  384
#define LK  384
#define DQ  32
#define DV  32
#define DC  64
#define BS  2

#define K2 2.8853900817779268f   // 2*log2(e)
#define FLT_BIG 3.4e38f

#define NQW (BS * H * LQ * DC)   // 393216
#define NKW (BS * H * DC * LK)   // 393216

// scratch: g_A[b,h,q,e] = exp(2*(q@W1_top + b1));  g_Ct[b,h,e,k] = exp(2*(k@W1_bot))
__device__ float g_A [BS * H * LQ * DC];
__device__ float g_Ct[BS * H * DC * LK];

__device__ __forceinline__ float ex2a(float x) {
    float r; asm("ex2.approx.f32 %0, %1;" : "=f"(r) : "f"(x)); return r;
}
__device__ __forceinline__ float rcpa(float x) {
    float r; asm("rcp.approx.f32 %0, %1;" : "=f"(r) : "f"(x)); return r;
}

// Fused precompute: first half of grid does e^{2A}, second half does e^{2C} (transposed).
__global__ void __launch_bounds__(256)
precompute(const float* __restrict__ q, const float* __restrict__ kin,
           const float* __restrict__ w1, const float* __restrict__ b1) {
    int gid = blockIdx.x * blockDim.x + threadIdx.x;
    if (gid < NQW) {
        int idx = gid;
        int e   = idx & (DC - 1);
        int row = idx >> 6;              // (b*H+h)*LQ + q
        int qi  = row % LQ;
        int bh  = row / LQ;
        int h   = bh & (H - 1);
        int b   = bh >> 3;
        const float* qrow = q + ((size_t)(b * LQ + qi)) * (H * DQ) + h * DQ;
        const float* w    = w1 + h * DC * DC + e;
        float a0 = b1[h * DC + e], a1 = 0.f;
#pragma unroll
        for (int d = 0; d < DQ; d += 2) {
            a0 = fmaf(qrow[d],     w[d * DC],        a0);
            a1 = fmaf(qrow[d + 1], w[(d + 1) * DC],  a1);
        }
        g_A[idx] = ex2a(K2 * (a0 + a1));           // e^{2A}
    } else {
        int idx  = gid - NQW;
        int kk   = idx % LK;
        int rest = idx / LK;             // (b*H+h)*DC + e
        int e    = rest & (DC - 1);
        int bh   = rest >> 6;
        int h    = bh & (H - 1);
        int b    = bh >> 3;
        const float* krow = kin + ((size_t)(b * LK + kk)) * (H * DQ) + h * DQ;
        const float* w    = w1 + h * DC * DC + DQ * DC + e;
        float a0 = 0.f, a1 = 0.f;
#pragma unroll
        for (int d = 0; d < DQ; d += 2) {
            a0 = fmaf(krow[d],     w[d * DC],       a0);
            a1 = fmaf(krow[d + 1], w[(d + 1) * DC], a1);
        }
        g_Ct[idx] = ex2a(K2 * (a0 + a1));          // e^{2C}, [e][k] layout
    }
}

// Block = 192 threads = 6 warps = 2 rows x 3 k-chunks (128 k each).
// tanh(A+C) = 1 - 2*r, r = 1/(tA*tC + 1); score = const - 2*acc, acc = sum_e w2*r;
// softmax(-2*acc) shift-invariant -> p = exp(2*(mn - acc)), mn = min over valid k.
__global__ void __launch_bounds__(192)
attn_kernel(const float* __restrict__ w2, const float* __restrict__ v,
            const int* __restrict__ qlen, const int* __restrict__ klen,
            float* __restrict__ out, float* __restrict__ att) {
    __shared__ float sTA [2][DC];        // e^{2A} per row
    __shared__ float sW2 [DC];           // w2[h,:] (h shared by both rows)
    __shared__ float sP  [2][LK];        // unnormalized probs
    __shared__ float sMn [2][3];
    __shared__ float sSum[2][3];
    __shared__ float sOut[2][3][DV];     // per-chunk AV partials

    int tid  = threadIdx.x;
    int warp = tid >> 5;
    int lane = tid & 31;
    int rl    = (warp >= 3) ? 1 : 0;
    int chunk = warp - rl * 3;

    int row0 = blockIdx.x * 2;
    int row  = row0 + rl;
    int qi   = row % LQ;
    int bh   = row / LQ;                 // same for both rows (384 rows per bh, even)
    int h    = bh & (H - 1);
    int b    = bh >> 3;

    if (tid < 128) {
        int r = tid >> 6, e = tid & 63;
        sTA[r][e] = g_A[(size_t)(row0 + r) * DC + e];
    }
    if (tid < 64) sW2[tid] = w2[h * DC + tid];
    __syncthreads();

    const int kl    = klen[b];
    const int kbase = chunk << 7;
    const float* ct = g_Ct + (size_t)bh * DC * LK;   // [e][k]

    // ---- pass 1: this warp's 128-k chunk, lane owns 4 consecutive k ----
    float s[4];
    if (kbase < kl) {
        const float* cp = ct + kbase + lane * 4;
        float a0 = 0.f, a1 = 0.f, a2 = 0.f, a3 = 0.f;
#pragma unroll 4
        for (int e4 = 0; e4 < DC / 4; e4++) {
            float4 ta = *(const float4*)&sTA[rl][e4 * 4];
            float4 wv = *(const float4*)&sW2[e4 * 4];
            const float* cpe = cp + e4 * 4 * LK;
            float4 c0 = *(const float4*)(cpe);
            float4 c1 = *(const float4*)(cpe + LK);
            float4 c2 = *(const float4*)(cpe + 2 * LK);
            float4 c3 = *(const float4*)(cpe + 3 * LK);
            a0 = fmaf(wv.x, rcpa(fmaf(ta.x, c0.x, 1.f)), a0);
            a1 = fmaf(wv.x, rcpa(fmaf(ta.x, c0.y, 1.f)), a1);
            a2 = fmaf(wv.x, rcpa(fmaf(ta.x, c0.z, 1.f)), a2);
            a3 = fmaf(wv.x, rcpa(fmaf(ta.x, c0.w, 1.f)), a3);
            a0 = fmaf(wv.y, rcpa(fmaf(ta.y, c1.x, 1.f)), a0);
            a1 = fmaf(wv.y, rcpa(fmaf(ta.y, c1.y, 1.f)), a1);
            a2 = fmaf(wv.y, rcpa(fmaf(ta.y, c1.z, 1.f)), a2);
            a3 = fmaf(wv.y, rcpa(fmaf(ta.y, c1.w, 1.f)), a3);
            a0 = fmaf(wv.z, rcpa(fmaf(ta.z, c2.x, 1.f)), a0);
            a1 = fmaf(wv.z, rcpa(fmaf(ta.z, c2.y, 1.f)), a1);
            a2 = fmaf(wv.z, rcpa(fmaf(ta.z, c2.z, 1.f)), a2);
            a3 = fmaf(wv.z, rcpa(fmaf(ta.z, c2.w, 1.f)), a3);
            a0 = fmaf(wv.w, rcpa(fmaf(ta.w, c3.x, 1.f)), a0);
            a1 = fmaf(wv.w, rcpa(fmaf(ta.w, c3.y, 1.f)), a1);
            a2 = fmaf(wv.w, rcpa(fmaf(ta.w, c3.z, 1.f)), a2);
            a3 = fmaf(wv.w, rcpa(fmaf(ta.w, c3.w, 1.f)), a3);
        }
        s[0] = a0; s[1] = a1; s[2] = a2; s[3] = a3;
    } else {
        s[0] = s[1] = s[2] = s[3] = FLT_BIG;
    }

    // ---- local min over valid k, then block-level min across 3 chunks ----
    float mn = FLT_BIG;
#pragma unroll
    for (int j = 0; j < 4; j++)
        if (kbase + lane * 4 + j < kl) mn = fminf(mn, s[j]);
#pragma unroll
    for (int o = 16; o; o >>= 1) mn = fminf(mn, __shfl_xor_sync(0xffffffffu, mn, o));
    if (lane == 0) sMn[rl][chunk] = mn;
    __syncthreads();
    mn = fminf(fminf(sMn[rl][0], sMn[rl][1]), sMn[rl][2]);

    // ---- pass 2: probs + partial sum ----
    float p[4];
    float sum = 0.f;
#pragma unroll
    for (int j = 0; j < 4; j++) {
        int kk = kbase + lane * 4 + j;
        float pv = (kk < kl) ? ex2a(K2 * (mn - s[j])) : 0.f;
        p[j] = pv;
        sum += pv;
    }
#pragma unroll
    for (int o = 16; o; o >>= 1) sum += __shfl_xor_sync(0xffffffffu, sum, o);
    if (lane == 0) sSum[rl][chunk] = sum;
    *(float4*)&sP[rl][kbase + lane * 4] = make_float4(p[0], p[1], p[2], p[3]);
    __syncthreads();

    float total = (sSum[rl][0] + sSum[rl][1]) + sSum[rl][2];
    float rinv  = 1.0f / total;

    // ---- att row (zeros beyond kl; d_out poisoned so must write all) ----
    *(float4*)(att + (size_t)row * LK + kbase + lane * 4) =
        make_float4(p[0] * rinv, p[1] * rinv, p[2] * rinv, p[3] * rinv);

    // ---- AV partial over this chunk, lane = dv ----
    float o = 0.f;
    if (kbase < kl) {
        int kcap = kl - kbase; if (kcap > 128) kcap = 128;
        const float* vb = v + ((size_t)(b * LK + kbase)) * (H * DV) + h * DV + lane;
        float o0 = 0.f, o1 = 0.f, o2 = 0.f, o3 = 0.f;
        int kk = 0;
#pragma unroll 8
        for (; kk + 4 <= kcap; kk += 4) {
            float4 pv = *(const float4*)&sP[rl][kbase + kk];
            o0 = fmaf(pv.x, vb[(size_t)(kk)     * (H * DV)], o0);
            o1 = fmaf(pv.y, vb[(size_t)(kk + 1) * (H * DV)], o1);
            o2 = fmaf(pv.z, vb[(size_t)(kk + 2) * (H * DV)], o2);
            o3 = fmaf(pv.w, vb[(size_t)(kk + 3) * (H * DV)], o3);
        }
        for (; kk < kcap; kk++)
            o0 = fmaf(sP[rl][kbase + kk], vb[(size_t)kk * (H * DV)], o0);
        o = (o0 + o1) + (o2 + o3);
    }
    sOut[rl][chunk][lane] = o;
    __syncthreads();

    if (chunk == 0) {
        float oo = ((sOut[rl][0][lane] + sOut[rl][1][lane]) + sOut[rl][2][lane]) * rinv;
        if (qi >= qlen[b]) oo = 0.f;
        out[((size_t)(b * LQ + qi)) * (H * DV) + h * DV + lane] = oo;
    }
}

extern "C" void kernel_launch(void* const* d_in, const int* in_sizes, int n_in,
                              void* d_out, int out_size) {
    const float* q    = (const float*)d_in[0];
    const float* k    = (const float*)d_in[1];
    const float* v    = (const float*)d_in[2];
    const int*   qlen = (const int*)  d_in[3];
    const int*   klen = (const int*)  d_in[4];
    const float* w1   = (const float*)d_in[5];
    const float* b1   = (const float*)d_in[6];
    const float* w2   = (const float*)d_in[7];

    float* out = (float*)d_out;
    float* att = out + (size_t)BS * LQ * H * DV;

    precompute<<<(NQW + NKW) / 256, 256>>>(q, k, w1, b1);
    attn_kernel<<<(BS * H * LQ) / 2, 192>>>(w2, v, qlen, klen, out, att);
}

// round 5
// speedup vs baseline: 1.7516x; 1.1340x over previous
#include <cuda_runtime.h>

#define H   8
#define LQ  384
#define LK  384
#define DQ  32
#define DV  32
#define DC  64
#define BS  2

#define K2 2.8853900817779268f   // 2*log2(e)
#define FLT_BIG 3.4e38f

#define NQW (BS * H * LQ * DC)   // 393216
#define NKW (BS * H * DC * LK)   // 393216

// scratch: g_A[b,h,q,e] = exp(2*(q@W1_top + b1));  g_Ct[b,h,e,k] = exp(2*(k@W1_bot))
__device__ float g_A [BS * H * LQ * DC];
__device__ float g_Ct[BS * H * DC * LK];

__device__ __forceinline__ float ex2a(float x) {
    float r; asm("ex2.approx.f32 %0, %1;" : "=f"(r) : "f"(x)); return r;
}
__device__ __forceinline__ float rcpa(float x) {
    float r; asm("rcp.approx.f32 %0, %1;" : "=f"(r) : "f"(x)); return r;
}

__global__ void __launch_bounds__(256)
precompute(const float* __restrict__ q, const float* __restrict__ kin,
           const float* __restrict__ w1, const float* __restrict__ b1) {
    int gid = blockIdx.x * blockDim.x + threadIdx.x;
    if (gid < NQW) {
        int idx = gid;
        int e   = idx & (DC - 1);
        int row = idx >> 6;
        int qi  = row % LQ;
        int bh  = row / LQ;
        int h   = bh & (H - 1);
        int b   = bh >> 3;
        const float* qrow = q + ((size_t)(b * LQ + qi)) * (H * DQ) + h * DQ;
        const float* w    = w1 + h * DC * DC + e;
        float a0 = b1[h * DC + e], a1 = 0.f;
#pragma unroll
        for (int d = 0; d < DQ; d += 2) {
            a0 = fmaf(qrow[d],     w[d * DC],        a0);
            a1 = fmaf(qrow[d + 1], w[(d + 1) * DC],  a1);
        }
        g_A[idx] = ex2a(K2 * (a0 + a1));           // e^{2A}
    } else {
        int idx  = gid - NQW;
        int kk   = idx % LK;
        int rest = idx / LK;
        int e    = rest & (DC - 1);
        int bh   = rest >> 6;
        int h    = bh & (H - 1);
        int b    = bh >> 3;
        const float* krow = kin + ((size_t)(b * LK + kk)) * (H * DQ) + h * DQ;
        const float* w    = w1 + h * DC * DC + DQ * DC + e;
        float a0 = 0.f, a1 = 0.f;
#pragma unroll
        for (int d = 0; d < DQ; d += 2) {
            a0 = fmaf(krow[d],     w[d * DC],       a0);
            a1 = fmaf(krow[d + 1], w[(d + 1) * DC], a1);
        }
        g_Ct[idx] = ex2a(K2 * (a0 + a1));          // e^{2C}, [e][k] layout
    }
}

// w0/d0 + w1/d1 = (w0*d1 + w1*d0) / (d0*d1): one rcp per TWO e-terms.
#define EPAIR(tax, tay, cx, cy, acc)                                   \
    {                                                                  \
        float d0_ = fmaf(tax, cx, 1.f), d1_ = fmaf(tay, cy, 1.f);      \
        float nu_ = fmaf(w.x, d1_, w.y * d0_);                         \
        acc = fmaf(nu_, rcpa(d0_ * d1_), acc);                         \
    }

// Block = 192 threads = 6 warps = 2 row-pairs x 3 k-chunks; 4 rows/block (same b,h).
// Each warp: 2 q-rows over one 128-k chunk; ct loads shared across the 2 rows.
__global__ void __launch_bounds__(192)
attn_kernel(const float* __restrict__ w2, const float* __restrict__ v,
            const int* __restrict__ qlen, const int* __restrict__ klen,
            float* __restrict__ out, float* __restrict__ att) {
    __shared__ float sTA [4][DC];        // e^{2A} per local row
    __shared__ float sW2 [DC];
    __shared__ float sP  [4][LK];        // unnormalized probs
    __shared__ float sMn [4][3];
    __shared__ float sSum[4][3];
    __shared__ float sOut[4][3][DV];     // per-chunk AV partials

    int tid  = threadIdx.x;
    int warp = tid >> 5;
    int lane = tid & 31;
    int rp    = (warp >= 3) ? 1 : 0;
    int chunk = warp - rp * 3;
    int rA = rp * 2, rB = rA + 1;        // this warp's local rows

    int row0 = blockIdx.x * 4;
    int rowA = row0 + rA, rowB = row0 + rB;
    int bh   = row0 / LQ;                // same for all 4 rows
    int h    = bh & (H - 1);
    int b    = bh >> 3;

    for (int i = tid; i < 4 * DC; i += 192)
        sTA[i >> 6][i & 63] = g_A[(size_t)(row0 + (i >> 6)) * DC + (i & 63)];
    if (tid < DC) sW2[tid] = w2[h * DC + tid];
    __syncthreads();

    const int kl    = klen[b];
    const int kbase = chunk << 7;
    const float* ct = g_Ct + (size_t)bh * DC * LK;   // [e][k]

    // ---- pass 1: 2 rows x 4 k per lane, e-pair combined ----
    float sa[4], sb[4];
    if (kbase < kl) {
        const float* cp = ct + kbase + lane * 4;
        float a0 = 0.f, a1 = 0.f, a2 = 0.f, a3 = 0.f;
        float b0 = 0.f, b1_ = 0.f, b2 = 0.f, b3 = 0.f;
#pragma unroll 8
        for (int ep = 0; ep < DC / 2; ep++) {
            float2 w  = *(const float2*)&sW2[2 * ep];
            float2 tA = *(const float2*)&sTA[rA][2 * ep];
            float2 tB = *(const float2*)&sTA[rB][2 * ep];
            float4 c0 = *(const float4*)(cp + (2 * ep) * LK);
            float4 c1 = *(const float4*)(cp + (2 * ep + 1) * LK);
            EPAIR(tA.x, tA.y, c0.x, c1.x, a0);
            EPAIR(tA.x, tA.y, c0.y, c1.y, a1);
            EPAIR(tA.x, tA.y, c0.z, c1.z, a2);
            EPAIR(tA.x, tA.y, c0.w, c1.w, a3);
            EPAIR(tB.x, tB.y, c0.x, c1.x, b0);
            EPAIR(tB.x, tB.y, c0.y, c1.y, b1_);
            EPAIR(tB.x, tB.y, c0.z, c1.z, b2);
            EPAIR(tB.x, tB.y, c0.w, c1.w, b3);
        }
        sa[0] = a0; sa[1] = a1; sa[2] = a2; sa[3] = a3;
        sb[0] = b0; sb[1] = b1_; sb[2] = b2; sb[3] = b3;
    } else {
#pragma unroll
        for (int j = 0; j < 4; j++) { sa[j] = FLT_BIG; sb[j] = FLT_BIG; }
    }

    // ---- min over valid k, block-combined across chunks ----
    float mnA = FLT_BIG, mnB = FLT_BIG;
#pragma unroll
    for (int j = 0; j < 4; j++) {
        if (kbase + lane * 4 + j < kl) {
            mnA = fminf(mnA, sa[j]);
            mnB = fminf(mnB, sb[j]);
        }
    }
#pragma unroll
    for (int o = 16; o; o >>= 1) {
        mnA = fminf(mnA, __shfl_xor_sync(0xffffffffu, mnA, o));
        mnB = fminf(mnB, __shfl_xor_sync(0xffffffffu, mnB, o));
    }
    if (lane == 0) { sMn[rA][chunk] = mnA; sMn[rB][chunk] = mnB; }
    __syncthreads();
    mnA = fminf(fminf(sMn[rA][0], sMn[rA][1]), sMn[rA][2]);
    mnB = fminf(fminf(sMn[rB][0], sMn[rB][1]), sMn[rB][2]);

    // ---- pass 2: probs + sums ----
    float pA[4], pB[4];
    float sumA = 0.f, sumB = 0.f;
#pragma unroll
    for (int j = 0; j < 4; j++) {
        int kk = kbase + lane * 4 + j;
        float pa = (kk < kl) ? ex2a(K2 * (mnA - sa[j])) : 0.f;
        float pb = (kk < kl) ? ex2a(K2 * (mnB - sb[j])) : 0.f;
        pA[j] = pa; pB[j] = pb;
        sumA += pa; sumB += pb;
    }
#pragma unroll
    for (int o = 16; o; o >>= 1) {
        sumA += __shfl_xor_sync(0xffffffffu, sumA, o);
        sumB += __shfl_xor_sync(0xffffffffu, sumB, o);
    }
    if (lane == 0) { sSum[rA][chunk] = sumA; sSum[rB][chunk] = sumB; }
    *(float4*)&sP[rA][kbase + lane * 4] = make_float4(pA[0], pA[1], pA[2], pA[3]);
    *(float4*)&sP[rB][kbase + lane * 4] = make_float4(pB[0], pB[1], pB[2], pB[3]);
    __syncthreads();

    float rinvA = 1.0f / ((sSum[rA][0] + sSum[rA][1]) + sSum[rA][2]);
    float rinvB = 1.0f / ((sSum[rB][0] + sSum[rB][1]) + sSum[rB][2]);

    // ---- att rows (zeros beyond kl) ----
    *(float4*)(att + (size_t)rowA * LK + kbase + lane * 4) =
        make_float4(pA[0] * rinvA, pA[1] * rinvA, pA[2] * rinvA, pA[3] * rinvA);
    *(float4*)(att + (size_t)rowB * LK + kbase + lane * 4) =
        make_float4(pB[0] * rinvB, pB[1] * rinvB, pB[2] * rinvB, pB[3] * rinvB);

    // ---- AV: lane -> (kg = k subgroup, dv4 = 4 dv values); float4 v loads shared by rows ----
    int kg  = lane >> 3;
    int dv4 = (lane & 7) << 2;
    float4 oA = make_float4(0.f, 0.f, 0.f, 0.f);
    float4 oB = make_float4(0.f, 0.f, 0.f, 0.f);
    int kcap = kl - kbase; if (kcap > 128) kcap = 128;
    const float* vb = v + ((size_t)(b * LK + kbase + kg)) * (H * DV) + h * DV + dv4;
    for (int kk = kg; kk < kcap; kk += 4, vb += 4 * (H * DV)) {
        float4 vv = *(const float4*)vb;
        float pa = sP[rA][kbase + kk];
        float pb = sP[rB][kbase + kk];
        oA.x = fmaf(pa, vv.x, oA.x); oA.y = fmaf(pa, vv.y, oA.y);
        oA.z = fmaf(pa, vv.z, oA.z); oA.w = fmaf(pa, vv.w, oA.w);
        oB.x = fmaf(pb, vv.x, oB.x); oB.y = fmaf(pb, vv.y, oB.y);
        oB.z = fmaf(pb, vv.z, oB.z); oB.w = fmaf(pb, vv.w, oB.w);
    }
#pragma unroll
    for (int o = 8; o <= 16; o <<= 1) {
        oA.x += __shfl_xor_sync(0xffffffffu, oA.x, o);
        oA.y += __shfl_xor_sync(0xffffffffu, oA.y, o);
        oA.z += __shfl_xor_sync(0xffffffffu, oA.z, o);
        oA.w += __shfl_xor_sync(0xffffffffu, oA.w, o);
        oB.x += __shfl_xor_sync(0xffffffffu, oB.x, o);
        oB.y += __shfl_xor_sync(0xffffffffu, oB.y, o);
        oB.z += __shfl_xor_sync(0xffffffffu, oB.z, o);
        oB.w += __shfl_xor_sync(0xffffffffu, oB.w, o);
    }
    if (kg == 0) {
        *(float4*)&sOut[rA][chunk][dv4] = oA;
        *(float4*)&sOut[rB][chunk][dv4] = oB;
    }
    __syncthreads();

    // ---- finalize: warps with chunk==0 write out for their 2 rows (lane = dv) ----
    if (chunk == 0) {
        const int ql = qlen[b];
        float ooA = ((sOut[rA][0][lane] + sOut[rA][1][lane]) + sOut[rA][2][lane]) * rinvA;
        float ooB = ((sOut[rB][0][lane] + sOut[rB][1][lane]) + sOut[rB][2][lane]) * rinvB;
        int qiA = rowA - bh * LQ;
        int qiB = rowB - bh * LQ;
        if (qiA >= ql) ooA = 0.f;
        if (qiB >= ql) ooB = 0.f;
        out[((size_t)(b * LQ + qiA)) * (H * DV) + h * DV + lane] = ooA;
        out[((size_t)(b * LQ + qiB)) * (H * DV) + h * DV + lane] = ooB;
    }
}

extern "C" void kernel_launch(void* const* d_in, const int* in_sizes, int n_in,
                              void* d_out, int out_size) {
    const float* q    = (const float*)d_in[0];
    const float* k    = (const float*)d_in[1];
    const float* v    = (const float*)d_in[2];
    const int*   qlen = (const int*)  d_in[3];
    const int*   klen = (const int*)  d_in[4];
    const float* w1   = (const float*)d_in[5];
    const float* b1   = (const float*)d_in[6];
    const float* w2   = (const float*)d_in[7];

    float* out = (float*)d_out;
    float* att = out + (size_t)BS * LQ * H * DV;

    precompute<<<(NQW + NKW) / 256, 256>>>(q, k, w1, b1);
    attn_kernel<<<(BS * H * LQ) / 4, 192>>>(w2, v, qlen, klen, out, att);
}